// round 12
// baseline (speedup 1.0000x reference)
#include <cuda_runtime.h>
#include <cuda_fp16.h>
#include <cstdint>

// Problem constants
#define Bn   4
#define Sn   2048
#define HIDn 2048
#define Hn   16
#define Dn   128
#define Mn   8192  // B*S

// Scratch (allocation-free rule: __device__ globals)
__device__ __half g_xh [(size_t)Mn * HIDn];            // x in fp16
__device__ __half g_wh [4][(size_t)HIDn * HIDn];       // Wq,Wk,Wv,Wo in fp16
__device__ __half g_qh [(size_t)Bn * Hn * Sn * Dn];    // Q fp16 [B,H,S,D]
__device__ __half g_kh [(size_t)Bn * Hn * Sn * Dn];    // K fp16 mirror
__device__ __half g_vh [(size_t)Bn * Hn * Sn * Dn];    // V fp16 mirror
__device__ __half g_ctx[(size_t)Mn * HIDn];            // ctx fp16 [B,S,H*D]

// ---------------------------------------------------------------------------
// helpers
// ---------------------------------------------------------------------------
__device__ __forceinline__ uint32_t smem_u32(const void* p) {
    uint32_t a;
    asm("{ .reg .u64 t; cvta.to.shared.u64 t, %1; cvt.u32.u64 %0, t; }"
        : "=r"(a) : "l"(p));
    return a;
}
__device__ __forceinline__ void cpasync16(uint32_t saddr, const void* g) {
    asm volatile("cp.async.cg.shared.global [%0], [%1], 16;" :: "r"(saddr), "l"(g));
}
__device__ __forceinline__ void mma_f16(float c[4], const uint32_t a[4], const uint32_t b[2]) {
    asm volatile("mma.sync.aligned.m16n8k16.row.col.f32.f16.f16.f32 "
                 "{%0,%1,%2,%3}, {%4,%5,%6,%7}, {%8,%9}, {%0,%1,%2,%3};"
                 : "+f"(c[0]), "+f"(c[1]), "+f"(c[2]), "+f"(c[3])
                 : "r"(a[0]), "r"(a[1]), "r"(a[2]), "r"(a[3]), "r"(b[0]), "r"(b[1]));
}
#define LDMX4(r, addr)                                                                  \
    asm volatile("ldmatrix.sync.aligned.m8n8.x4.shared.b16 {%0,%1,%2,%3}, [%4];"        \
                 : "=r"((r)[0]), "=r"((r)[1]), "=r"((r)[2]), "=r"((r)[3]) : "r"(addr))
#define LDMX4T(r, addr)                                                                 \
    asm volatile("ldmatrix.sync.aligned.m8n8.x4.trans.shared.b16 {%0,%1,%2,%3}, [%4];"  \
                 : "=r"((r)[0]), "=r"((r)[1]), "=r"((r)[2]), "=r"((r)[3]) : "r"(addr))

// ---------------------------------------------------------------------------
// fp32 -> fp16 conversion prepass
// ---------------------------------------------------------------------------
__global__ void __launch_bounds__(256) f2h(const float4* __restrict__ in,
                                           uint2* __restrict__ out, int n4) {
    int i = blockIdx.x * blockDim.x + threadIdx.x;
    if (i < n4) {
        float4 v = in[i];
        __half2 a = __floats2half2_rn(v.x, v.y);
        __half2 b = __floats2half2_rn(v.z, v.w);
        uint2 r;
        r.x = *reinterpret_cast<uint32_t*>(&a);
        r.y = *reinterpret_cast<uint32_t*>(&b);
        out[i] = r;
    }
}
__global__ void __launch_bounds__(256) f2h_w4(const float4* __restrict__ w0,
                                              const float4* __restrict__ w1,
                                              const float4* __restrict__ w2,
                                              const float4* __restrict__ w3,
                                              uint2* __restrict__ out, int n4) {
    const float4* srcs[4] = {w0, w1, w2, w3};
    const float4* in = srcs[blockIdx.y];
    uint2* dst = out + (size_t)blockIdx.y * n4;
    int i = blockIdx.x * blockDim.x + threadIdx.x;
    if (i < n4) {
        float4 v = in[i];
        __half2 a = __floats2half2_rn(v.x, v.y);
        __half2 b = __floats2half2_rn(v.z, v.w);
        uint2 r;
        r.x = *reinterpret_cast<uint32_t*>(&a);
        r.y = *reinterpret_cast<uint32_t*>(&b);
        dst[i] = r;
    }
}

// ---------------------------------------------------------------------------
// fp16 mma.sync NT-GEMM: C[128x128] CTA tile, 128 threads = 4 warps (2m x 2n),
// warp tile 64x64, BK=32. 3-stage cp.async, one __syncthreads per K-iter.
// Per k16: 4 A-ldmatrix + 4 B-ldmatrix -> 32 MMAs (4:1), 2 CTAs/SM.
// MODE 0: QKV projection (z selects W); MODE 1: output projection.
// ---------------------------------------------------------------------------
#define GLDW 40
#define STG_H (256 * GLDW)              // A(128)+B(128) rows, halves
#define NSTG 3
#define GEMM_SMEM (NSTG * STG_H * 2)    // 61440 B

template<int MODE>
__global__ void __launch_bounds__(128, 2) gemm_mma(const __half* __restrict__ A_,
                                                   const __half* __restrict__ W0,
                                                   const __half* __restrict__ W1,
                                                   const __half* __restrict__ W2,
                                                   float* __restrict__ fout,
                                                   __half* __restrict__ hq,
                                                   __half* __restrict__ hk,
                                                   __half* __restrict__ hv)
{
    extern __shared__ __half smh[];

    const int tid  = threadIdx.x;
    const int wid  = tid >> 5;          // 0..3
    const int lane = tid & 31;
    const int wm = (wid >> 1) * 64;     // 2 m-warps
    const int wn = (wid & 1) * 64;      // 2 n-warps

    const int m0 = blockIdx.y * 128;
    const int n0 = blockIdx.x * 128;
    int z = 0;
    const __half* W = W0;
    if (MODE == 0) { z = blockIdx.z; W = (z == 0) ? W0 : (z == 1) ? W1 : W2; }

    const int mat = lane >> 3;
    const int a_r = (mat & 1) * 8 + (lane & 7);
    const int a_c = (mat >> 1) * 8;
    const int bx_r = (lane >> 4) * 8 + (lane & 7);
    const int bx_c = ((lane >> 3) & 1) * 8;

    float acc[4][8][4] = {};

    auto load_stage = [&](int j) {
        __half* As = smh + (j % NSTG) * STG_H;
        __half* Bs = As + 128 * GLDW;
        const int k0 = j * 32;
        #pragma unroll
        for (int i = 0; i < 8; i++) {
            int idx = tid + i * 128;            // 0..1023
            int row = idx >> 2;                 // 0..255
            int c   = idx & 3;                  // 16B chunk (8 halves)
            if (row < 128) {
                cpasync16(smem_u32(As + row * GLDW + c * 8),
                          A_ + (size_t)(m0 + row) * HIDn + k0 + c * 8);
            } else {
                int r = row - 128;
                cpasync16(smem_u32(Bs + r * GLDW + c * 8),
                          W + (size_t)(n0 + r) * HIDn + k0 + c * 8);
            }
        }
        asm volatile("cp.async.commit_group;");
    };

    const int nk = HIDn / 32;                   // 64
    load_stage(0);
    load_stage(1);

    for (int j = 0; j < nk; j++) {
        if (j < nk - 2) {
            asm volatile("cp.async.wait_group 1;" ::: "memory");
        } else {
            asm volatile("cp.async.wait_group 0;" ::: "memory");
        }
        __syncthreads();
        if (j + 2 < nk) load_stage(j + 2);

        const __half* As = smh + (j % NSTG) * STG_H;
        const __half* Bs = As + 128 * GLDW;

        #pragma unroll
        for (int ks = 0; ks < 2; ks++) {
            const int k0 = ks * 16;
            uint32_t a[4][4];
            #pragma unroll
            for (int i = 0; i < 4; i++)
                LDMX4(a[i], smem_u32(As + (wm + i * 16 + a_r) * GLDW + k0 + a_c));
            uint32_t b4[4][4];
            #pragma unroll
            for (int tp = 0; tp < 4; tp++)
                LDMX4(b4[tp], smem_u32(Bs + (wn + tp * 16 + bx_r) * GLDW + k0 + bx_c));
            #pragma unroll
            for (int i = 0; i < 4; i++)
                #pragma unroll
                for (int t = 0; t < 8; t++)
                    mma_f16(acc[i][t], a[i], &b4[t >> 1][(t & 1) * 2]);
        }
    }

    const int er = lane >> 2;
    const int ec = (lane & 3) * 2;

    #pragma unroll
    for (int i = 0; i < 4; i++) {
        const int rg = m0 + wm + i * 16 + er;
        #pragma unroll
        for (int half = 0; half < 2; half++) {
            const int m = rg + half * 8;
            if (MODE == 1) {
                size_t o = (size_t)m * HIDn + n0 + wn + ec;
                #pragma unroll
                for (int t = 0; t < 8; t++) {
                    float2 v = make_float2(acc[i][t][half * 2], acc[i][t][half * 2 + 1]);
                    *reinterpret_cast<float2*>(fout + o + t * 8) = v;
                }
            } else {
                const int b = m >> 11;
                const int s = m & (Sn - 1);
                const int h = n0 >> 7;              // N tile 128 = one head
                const int d0 = wn + ec;
                size_t hb = (((size_t)(b * Hn + h)) * Sn + s) * Dn + d0;
                if (z == 0) {
                    #pragma unroll
                    for (int t = 0; t < 8; t++) {
                        __half2 hv2 = __floats2half2_rn(acc[i][t][half * 2], acc[i][t][half * 2 + 1]);
                        *reinterpret_cast<__half2*>(hq + hb + t * 8) = hv2;
                    }
                } else {
                    size_t fb = ((((size_t)(b * Hn + h)) * 2 + (z - 1)) * Sn + s) * Dn + d0;
                    __half* hm = (z == 1) ? hk : hv;
                    #pragma unroll
                    for (int t = 0; t < 8; t++) {
                        float2 v = make_float2(acc[i][t][half * 2], acc[i][t][half * 2 + 1]);
                        *reinterpret_cast<float2*>(fout + fb + t * 8) = v;
                        __half2 hv2 = __floats2half2_rn(v.x, v.y);
                        *reinterpret_cast<__half2*>(hm + hb + t * 8) = hv2;
                    }
                }
            }
        }
    }
}

// ---------------------------------------------------------------------------
// fp16 tensor-core causal flash attention (R8 config, measured best:
// 128 q-rows, 8 warps, cp.async double-buffered K/V).
// ---------------------------------------------------------------------------
#define LDQ 136
#define LDK 136
#define LDP 72
#define KVBUF_H (64 * LDK)
#define OFF_KV  0
#define OFF_PS  (4 * KVBUF_H)                    // 34816
#define OFF_QS  (OFF_PS + 128 * LDP)             // 44032
#define ATT_SMEM_H (OFF_QS + 128 * LDQ)          // 61440 halves
#define ATT_SMEM_B (ATT_SMEM_H * 2)              // 122880 bytes

__global__ void __launch_bounds__(256, 1) attn_mma(const __half* __restrict__ q,
                                                   const __half* __restrict__ kh,
                                                   const __half* __restrict__ vh,
                                                   __half* __restrict__ ctx)
{
    extern __shared__ __half smh[];
    __half* Psh = smh + OFF_PS;   // [128][LDP]
    __half* Qs  = smh + OFF_QS;   // [128][LDQ]

    const int q0 = blockIdx.x * 128;
    const int bh = blockIdx.y;
    const __half* qb = q  + (size_t)bh * Sn * Dn;
    const __half* kb = kh + (size_t)bh * Sn * Dn;
    const __half* vb = vh + (size_t)bh * Sn * Dn;

    const int tid  = threadIdx.x;
    const int wid  = tid >> 5;
    const int lane = tid & 31;
    const int w16  = wid * 16;

    const int mat = lane >> 3;
    const int a_r = (mat & 1) * 8 + (lane & 7);
    const int a_c = (mat >> 1) * 8;
    const int b_r = (lane >> 4) * 8 + (lane & 7);
    const int b_c = ((lane >> 3) & 1) * 8;
    const int v_r = ((lane >> 3) & 1) * 8 + (lane & 7);
    const int v_c = (lane >> 4) * 8;

    auto load_kv = [&](int jt) {
        __half* Kb = smh + OFF_KV + (jt & 1) * 2 * KVBUF_H;
        __half* Vb = Kb + KVBUF_H;
        const int j0 = jt * 64;
        #pragma unroll
        for (int i = 0; i < 4; i++) {
            int idx = tid + i * 256;
            int row = idx >> 4;
            int c   = idx & 15;
            cpasync16(smem_u32(Kb + row * LDK + c * 8),
                      kb + (size_t)(j0 + row) * Dn + c * 8);
            cpasync16(smem_u32(Vb + row * LDK + c * 8),
                      vb + (size_t)(j0 + row) * Dn + c * 8);
        }
        asm volatile("cp.async.commit_group;");
    };

    #pragma unroll
    for (int i = 0; i < 8; i++) {
        int idx = tid + i * 256;
        int row = idx >> 4;
        int c   = idx & 15;
        cpasync16(smem_u32(Qs + row * LDQ + c * 8),
                  qb + (size_t)(q0 + row) * Dn + c * 8);
    }
    asm volatile("cp.async.commit_group;");
    load_kv(0);
    asm volatile("cp.async.wait_group 0;" ::: "memory");
    __syncthreads();

    uint32_t qa[8][4];
    #pragma unroll
    for (int ks = 0; ks < 8; ks++)
        LDMX4(qa[ks], smem_u32(Qs + (w16 + a_r) * LDQ + ks * 16 + a_c));

    float acc[16][4] = {};
    float m0r = -1e30f, m1r = -1e30f, l0r = 0.0f, l1r = 0.0f;
    const float scale = 0.08838834764831845f;
    const int r0 = lane >> 2;
    const int pc = (lane & 3) * 2;
    const int qg0 = q0 + w16 + r0;
    const int qg1 = qg0 + 8;
    const int nkt = (q0 >> 6) + 2;

    for (int jt = 0; jt < nkt; jt++) {
        const int j0 = jt * 64;

        if (jt > 0) {
            asm volatile("cp.async.wait_group 0;" ::: "memory");
            __syncthreads();
        }
        if (jt + 1 < nkt) load_kv(jt + 1);

        const __half* Ks = smh + OFF_KV + (jt & 1) * 2 * KVBUF_H;
        const __half* Vs = Ks + KVBUF_H;

        float sc[8][4] = {};
        #pragma unroll
        for (int ks = 0; ks < 8; ks++) {
            uint32_t kb4[4][4];
            #pragma unroll
            for (int tp = 0; tp < 4; tp++)
                LDMX4(kb4[tp], smem_u32(Ks + (tp * 16 + b_r) * LDK + ks * 16 + b_c));
            #pragma unroll
            for (int t = 0; t < 8; t++)
                mma_f16(sc[t], qa[ks], &kb4[t >> 1][(t & 1) * 2]);
        }

        if (j0 + 63 > q0 + w16) {
            #pragma unroll
            for (int t = 0; t < 8; t++) {
                int c0 = j0 + t * 8 + pc;
                sc[t][0] = (c0     <= qg0) ? sc[t][0] * scale : -1e30f;
                sc[t][1] = (c0 + 1 <= qg0) ? sc[t][1] * scale : -1e30f;
                sc[t][2] = (c0     <= qg1) ? sc[t][2] * scale : -1e30f;
                sc[t][3] = (c0 + 1 <= qg1) ? sc[t][3] * scale : -1e30f;
            }
        } else {
            #pragma unroll
            for (int t = 0; t < 8; t++) {
                sc[t][0] *= scale; sc[t][1] *= scale;
                sc[t][2] *= scale; sc[t][3] *= scale;
            }
        }

        float mx0 = -1e30f, mx1 = -1e30f;
        #pragma unroll
        for (int t = 0; t < 8; t++) {
            mx0 = fmaxf(mx0, fmaxf(sc[t][0], sc[t][1]));
            mx1 = fmaxf(mx1, fmaxf(sc[t][2], sc[t][3]));
        }
        mx0 = fmaxf(mx0, __shfl_xor_sync(0xffffffffu, mx0, 1));
        mx0 = fmaxf(mx0, __shfl_xor_sync(0xffffffffu, mx0, 2));
        mx1 = fmaxf(mx1, __shfl_xor_sync(0xffffffffu, mx1, 1));
        mx1 = fmaxf(mx1, __shfl_xor_sync(0xffffffffu, mx1, 2));

        float nm0 = fmaxf(m0r, mx0), nm1 = fmaxf(m1r, mx1);
        float al0 = __expf(m0r - nm0), al1 = __expf(m1r - nm1);
        m0r = nm0; m1r = nm1;

        float s0 = 0.0f, s1 = 0.0f;
        #pragma unroll
        for (int t = 0; t < 8; t++) {
            sc[t][0] = __expf(sc[t][0] - nm0);
            sc[t][1] = __expf(sc[t][1] - nm0);
            sc[t][2] = __expf(sc[t][2] - nm1);
            sc[t][3] = __expf(sc[t][3] - nm1);
            s0 += sc[t][0] + sc[t][1];
            s1 += sc[t][2] + sc[t][3];
        }
        s0 += __shfl_xor_sync(0xffffffffu, s0, 1);
        s0 += __shfl_xor_sync(0xffffffffu, s0, 2);
        s1 += __shfl_xor_sync(0xffffffffu, s1, 1);
        s1 += __shfl_xor_sync(0xffffffffu, s1, 2);
        l0r = l0r * al0 + s0;
        l1r = l1r * al1 + s1;

        #pragma unroll
        for (int t = 0; t < 16; t++) {
            acc[t][0] *= al0; acc[t][1] *= al0;
            acc[t][2] *= al1; acc[t][3] *= al1;
        }

        #pragma unroll
        for (int t = 0; t < 8; t++) {
            *reinterpret_cast<__half2*>(Psh + (w16 + r0)     * LDP + t * 8 + pc) =
                __floats2half2_rn(sc[t][0], sc[t][1]);
            *reinterpret_cast<__half2*>(Psh + (w16 + r0 + 8) * LDP + t * 8 + pc) =
                __floats2half2_rn(sc[t][2], sc[t][3]);
        }
        __syncwarp();

        #pragma unroll
        for (int kp = 0; kp < 4; kp++) {
            uint32_t pa[4];
            LDMX4(pa, smem_u32(Psh + (w16 + a_r) * LDP + kp * 16 + a_c));
            #pragma unroll
            for (int dp = 0; dp < 8; dp++) {
                uint32_t vb4[4];
                LDMX4T(vb4, smem_u32(Vs + (kp * 16 + v_r) * LDK + dp * 16 + v_c));
                mma_f16(acc[dp * 2],     pa, &vb4[0]);
                mma_f16(acc[dp * 2 + 1], pa, &vb4[2]);
            }
        }
    }

    const int b = bh >> 4;
    const int h = bh & 15;
    const float inv0 = 1.0f / l0r;
    const float inv1 = 1.0f / l1r;
    size_t base0 = ((size_t)b * Sn + qg0) * (Hn * Dn) + h * Dn + pc;
    size_t base1 = ((size_t)b * Sn + qg1) * (Hn * Dn) + h * Dn + pc;
    #pragma unroll
    for (int t = 0; t < 16; t++) {
        *reinterpret_cast<__half2*>(ctx + base0 + t * 8) =
            __floats2half2_rn(acc[t][0] * inv0, acc[t][1] * inv0);
        *reinterpret_cast<__half2*>(ctx + base1 + t * 8) =
            __floats2half2_rn(acc[t][2] * inv1, acc[t][3] * inv1);
    }
}

// ---------------------------------------------------------------------------
// Launch
// ---------------------------------------------------------------------------
extern "C" void kernel_launch(void* const* d_in, const int* in_sizes, int n_in,
                              void* d_out, int out_size)
{
    const float* x  = (const float*)d_in[0];
    const float* Wq = (const float*)d_in[1];
    const float* Wk = (const float*)d_in[2];
    const float* Wv = (const float*)d_in[3];
    const float* Wo = (const float*)d_in[4];

    float* out = (float*)d_out;                    // [B,S,HID]
    float* kv  = out + (size_t)Bn * Sn * HIDn;     // [B,H,2,S,D]

    __half *xh, *wh, *qh, *kh, *vh, *ctxh;
    cudaGetSymbolAddress((void**)&xh,   g_xh);
    cudaGetSymbolAddress((void**)&wh,   g_wh);
    cudaGetSymbolAddress((void**)&qh,   g_qh);
    cudaGetSymbolAddress((void**)&kh,   g_kh);
    cudaGetSymbolAddress((void**)&vh,   g_vh);
    cudaGetSymbolAddress((void**)&ctxh, g_ctx);

    // 0) convert inputs to fp16 (2 launches)
    {
        int n4x = Mn * HIDn / 4;
        int n4w = HIDn * HIDn / 4;
        f2h<<<(n4x + 255) / 256, 256>>>((const float4*)x, (uint2*)xh, n4x);
        dim3 gw((n4w + 255) / 256, 4);
        f2h_w4<<<gw, 256>>>((const float4*)Wq, (const float4*)Wk,
                            (const float4*)Wv, (const float4*)Wo,
                            (uint2*)wh, n4w);
    }

    // 1) Q/K/V projections (K,V fp32 straight into kv cache + fp16 mirrors)
    cudaFuncSetAttribute(gemm_mma<0>, cudaFuncAttributeMaxDynamicSharedMemorySize, GEMM_SMEM);
    cudaFuncSetAttribute(gemm_mma<1>, cudaFuncAttributeMaxDynamicSharedMemorySize, GEMM_SMEM);
    dim3 gproj(HIDn / 128, Mn / 128, 3);
    gemm_mma<0><<<gproj, 128, GEMM_SMEM>>>(xh,
                                           wh + 0 * (size_t)HIDn * HIDn,
                                           wh + 1 * (size_t)HIDn * HIDn,
                                           wh + 2 * (size_t)HIDn * HIDn,
                                           kv, qh, kh, vh);

    // 2) causal flash attention (fp16 tensor cores)
    cudaFuncSetAttribute(attn_mma, cudaFuncAttributeMaxDynamicSharedMemorySize, ATT_SMEM_B);
    dim3 gattn(Sn / 128, Bn * Hn);
    attn_mma<<<gattn, 256, ATT_SMEM_B>>>(qh, kh, vh, ctxh);

    // 3) output projection (fp32 result)
    dim3 gout(HIDn / 128, Mn / 128, 1);
    gemm_mma<1><<<gout, 128, GEMM_SMEM>>>(ctxh,
                                          wh + 3 * (size_t)HIDn * HIDn,
                                          nullptr, nullptr,
                                          out, nullptr, nullptr, nullptr);
}

// round 13
// speedup vs baseline: 1.4918x; 1.4918x over previous
#include <cuda_runtime.h>
#include <cuda_fp16.h>
#include <cstdint>

// Problem constants
#define Bn   4
#define Sn   2048
#define HIDn 2048
#define Hn   16
#define Dn   128
#define Mn   8192  // B*S

// Scratch (allocation-free rule: __device__ globals)
__device__ __half g_xh [(size_t)Mn * HIDn];            // x in fp16
__device__ __half g_wh [4][(size_t)HIDn * HIDn];       // Wq,Wk,Wv,Wo in fp16
__device__ __half g_qh [(size_t)Bn * Hn * Sn * Dn];    // Q fp16 [B,H,S,D]
__device__ __half g_kh [(size_t)Bn * Hn * Sn * Dn];    // K fp16 mirror
__device__ __half g_vh [(size_t)Bn * Hn * Sn * Dn];    // V fp16 mirror
__device__ __half g_ctx[(size_t)Mn * HIDn];            // ctx fp16 [B,S,H*D]

// ---------------------------------------------------------------------------
// helpers
// ---------------------------------------------------------------------------
__device__ __forceinline__ uint32_t smem_u32(const void* p) {
    uint32_t a;
    asm("{ .reg .u64 t; cvta.to.shared.u64 t, %1; cvt.u32.u64 %0, t; }"
        : "=r"(a) : "l"(p));
    return a;
}
__device__ __forceinline__ void cpasync16(uint32_t saddr, const void* g) {
    asm volatile("cp.async.cg.shared.global [%0], [%1], 16;" :: "r"(saddr), "l"(g));
}
__device__ __forceinline__ void mma_f16(float c[4], const uint32_t a[4], const uint32_t b[2]) {
    asm volatile("mma.sync.aligned.m16n8k16.row.col.f32.f16.f16.f32 "
                 "{%0,%1,%2,%3}, {%4,%5,%6,%7}, {%8,%9}, {%0,%1,%2,%3};"
                 : "+f"(c[0]), "+f"(c[1]), "+f"(c[2]), "+f"(c[3])
                 : "r"(a[0]), "r"(a[1]), "r"(a[2]), "r"(a[3]), "r"(b[0]), "r"(b[1]));
}
#define LDMX4(r, addr)                                                                  \
    asm volatile("ldmatrix.sync.aligned.m8n8.x4.shared.b16 {%0,%1,%2,%3}, [%4];"        \
                 : "=r"((r)[0]), "=r"((r)[1]), "=r"((r)[2]), "=r"((r)[3]) : "r"(addr))
#define LDMX4T(r, addr)                                                                 \
    asm volatile("ldmatrix.sync.aligned.m8n8.x4.trans.shared.b16 {%0,%1,%2,%3}, [%4];"  \
                 : "=r"((r)[0]), "=r"((r)[1]), "=r"((r)[2]), "=r"((r)[3]) : "r"(addr))

// ---------------------------------------------------------------------------
// fp32 -> fp16 conversion prepass
// ---------------------------------------------------------------------------
__global__ void __launch_bounds__(256) f2h(const float4* __restrict__ in,
                                           uint2* __restrict__ out, int n4) {
    int i = blockIdx.x * blockDim.x + threadIdx.x;
    if (i < n4) {
        float4 v = in[i];
        __half2 a = __floats2half2_rn(v.x, v.y);
        __half2 b = __floats2half2_rn(v.z, v.w);
        uint2 r;
        r.x = *reinterpret_cast<uint32_t*>(&a);
        r.y = *reinterpret_cast<uint32_t*>(&b);
        out[i] = r;
    }
}
__global__ void __launch_bounds__(256) f2h_w4(const float4* __restrict__ w0,
                                              const float4* __restrict__ w1,
                                              const float4* __restrict__ w2,
                                              const float4* __restrict__ w3,
                                              uint2* __restrict__ out, int n4) {
    const float4* srcs[4] = {w0, w1, w2, w3};
    const float4* in = srcs[blockIdx.y];
    uint2* dst = out + (size_t)blockIdx.y * n4;
    int i = blockIdx.x * blockDim.x + threadIdx.x;
    if (i < n4) {
        float4 v = in[i];
        __half2 a = __floats2half2_rn(v.x, v.y);
        __half2 b = __floats2half2_rn(v.z, v.w);
        uint2 r;
        r.x = *reinterpret_cast<uint32_t*>(&a);
        r.y = *reinterpret_cast<uint32_t*>(&b);
        dst[i] = r;
    }
}

// ---------------------------------------------------------------------------
// fp16 mma.sync NT-GEMM (EXACT R8 config: 256 thr = 8 warps 2m x 4n,
// warp tile 64x32, BK=32, 3-stage cp.async, 2 CTAs/SM)
// ---------------------------------------------------------------------------
#define LDW 40
#define TILE_H (128 * LDW)
#define STAGE_H (2 * TILE_H)
#define NSTG 3
#define GEMM_SMEM (NSTG * STAGE_H * 2)

template<int MODE>
__global__ void __launch_bounds__(256, 2) gemm_mma(const __half* __restrict__ A_,
                                                   const __half* __restrict__ W0,
                                                   const __half* __restrict__ W1,
                                                   const __half* __restrict__ W2,
                                                   float* __restrict__ fout,
                                                   __half* __restrict__ hq,
                                                   __half* __restrict__ hk,
                                                   __half* __restrict__ hv)
{
    extern __shared__ __half smh[];

    const int tid  = threadIdx.x;
    const int wid  = tid >> 5;
    const int lane = tid & 31;
    const int wm = (wid >> 2) * 64;
    const int wn = (wid & 3) * 32;

    const int m0 = blockIdx.y * 128;
    const int n0 = blockIdx.x * 128;
    int z = 0;
    const __half* W = W0;
    if (MODE == 0) { z = blockIdx.z; W = (z == 0) ? W0 : (z == 1) ? W1 : W2; }

    const int mat = lane >> 3;
    const int a_r = (mat & 1) * 8 + (lane & 7);
    const int a_c = (mat >> 1) * 8;
    const int bx_r = (lane >> 4) * 8 + (lane & 7);
    const int bx_c = ((lane >> 3) & 1) * 8;

    float acc[4][4][4] = {};

    auto load_stage = [&](int j) {
        __half* As = smh + (j % NSTG) * STAGE_H;
        __half* Bs = As + TILE_H;
        const int k0 = j * 32;
        #pragma unroll
        for (int i = 0; i < 2; i++) {
            int idx = tid + i * 256;
            int row = idx >> 2;
            int c   = idx & 3;
            cpasync16(smem_u32(As + row * LDW + c * 8),
                      A_ + (size_t)(m0 + row) * HIDn + k0 + c * 8);
            cpasync16(smem_u32(Bs + row * LDW + c * 8),
                      W  + (size_t)(n0 + row) * HIDn + k0 + c * 8);
        }
        asm volatile("cp.async.commit_group;");
    };

    const int nk = HIDn / 32;
    load_stage(0);
    load_stage(1);

    for (int j = 0; j < nk; j++) {
        if (j < nk - 2) {
            asm volatile("cp.async.wait_group 1;" ::: "memory");
        } else {
            asm volatile("cp.async.wait_group 0;" ::: "memory");
        }
        __syncthreads();
        if (j + 2 < nk) load_stage(j + 2);

        const __half* As = smh + (j % NSTG) * STAGE_H;
        const __half* Bs = As + TILE_H;

        #pragma unroll
        for (int ks = 0; ks < 2; ks++) {
            const int k0 = ks * 16;
            uint32_t a[4][4];
            #pragma unroll
            for (int i = 0; i < 4; i++)
                LDMX4(a[i], smem_u32(As + (wm + i * 16 + a_r) * LDW + k0 + a_c));
            uint32_t b4[2][4];
            #pragma unroll
            for (int tp = 0; tp < 2; tp++)
                LDMX4(b4[tp], smem_u32(Bs + (wn + tp * 16 + bx_r) * LDW + k0 + bx_c));
            #pragma unroll
            for (int i = 0; i < 4; i++)
                #pragma unroll
                for (int t = 0; t < 4; t++)
                    mma_f16(acc[i][t], a[i], &b4[t >> 1][(t & 1) * 2]);
        }
    }

    const int er = lane >> 2;
    const int ec = (lane & 3) * 2;

    #pragma unroll
    for (int i = 0; i < 4; i++) {
        const int r0 = m0 + wm + i * 16 + er;
        #pragma unroll
        for (int half = 0; half < 2; half++) {
            const int m = r0 + half * 8;
            if (MODE == 1) {
                size_t o = (size_t)m * HIDn + n0 + wn + ec;
                #pragma unroll
                for (int t = 0; t < 4; t++) {
                    float2 v = make_float2(acc[i][t][half * 2], acc[i][t][half * 2 + 1]);
                    *reinterpret_cast<float2*>(fout + o + t * 8) = v;
                }
            } else {
                const int b = m >> 11;
                const int s = m & (Sn - 1);
                const int h = n0 >> 7;
                const int d0 = wn + ec;
                size_t hb = (((size_t)(b * Hn + h)) * Sn + s) * Dn + d0;
                if (z == 0) {
                    #pragma unroll
                    for (int t = 0; t < 4; t++) {
                        __half2 hv2 = __floats2half2_rn(acc[i][t][half * 2], acc[i][t][half * 2 + 1]);
                        *reinterpret_cast<__half2*>(hq + hb + t * 8) = hv2;
                    }
                } else {
                    size_t fb = ((((size_t)(b * Hn + h)) * 2 + (z - 1)) * Sn + s) * Dn + d0;
                    __half* hm = (z == 1) ? hk : hv;
                    #pragma unroll
                    for (int t = 0; t < 4; t++) {
                        float2 v = make_float2(acc[i][t][half * 2], acc[i][t][half * 2 + 1]);
                        *reinterpret_cast<float2*>(fout + fb + t * 8) = v;
                        __half2 hv2 = __floats2half2_rn(v.x, v.y);
                        *reinterpret_cast<__half2*>(hm + hb + t * 8) = hv2;
                    }
                }
            }
        }
    }
}

// ---------------------------------------------------------------------------
// fp16 tensor-core causal flash attention (R8 config) + LPT scheduling:
// q-tile = gridDim.x-1-blockIdx.x so heaviest (largest q0) CTAs launch first.
// ---------------------------------------------------------------------------
#define LDQ 136
#define LDK 136
#define LDP 72
#define KVBUF_H (64 * LDK)
#define OFF_KV  0
#define OFF_PS  (4 * KVBUF_H)                    // 34816
#define OFF_QS  (OFF_PS + 128 * LDP)             // 44032
#define ATT_SMEM_H (OFF_QS + 128 * LDQ)          // 61440 halves
#define ATT_SMEM_B (ATT_SMEM_H * 2)              // 122880 bytes

__global__ void __launch_bounds__(256, 1) attn_mma(const __half* __restrict__ q,
                                                   const __half* __restrict__ kh,
                                                   const __half* __restrict__ vh,
                                                   __half* __restrict__ ctx)
{
    extern __shared__ __half smh[];
    __half* Psh = smh + OFF_PS;   // [128][LDP]
    __half* Qs  = smh + OFF_QS;   // [128][LDQ]

    const int qt = gridDim.x - 1 - blockIdx.x;    // LPT: heavy tiles first
    const int q0 = qt * 128;
    const int bh = blockIdx.y;
    const __half* qb = q  + (size_t)bh * Sn * Dn;
    const __half* kb = kh + (size_t)bh * Sn * Dn;
    const __half* vb = vh + (size_t)bh * Sn * Dn;

    const int tid  = threadIdx.x;
    const int wid  = tid >> 5;
    const int lane = tid & 31;
    const int w16  = wid * 16;

    const int mat = lane >> 3;
    const int a_r = (mat & 1) * 8 + (lane & 7);
    const int a_c = (mat >> 1) * 8;
    const int b_r = (lane >> 4) * 8 + (lane & 7);
    const int b_c = ((lane >> 3) & 1) * 8;
    const int v_r = ((lane >> 3) & 1) * 8 + (lane & 7);
    const int v_c = (lane >> 4) * 8;

    auto load_kv = [&](int jt) {
        __half* Kb = smh + OFF_KV + (jt & 1) * 2 * KVBUF_H;
        __half* Vb = Kb + KVBUF_H;
        const int j0 = jt * 64;
        #pragma unroll
        for (int i = 0; i < 4; i++) {
            int idx = tid + i * 256;
            int row = idx >> 4;
            int c   = idx & 15;
            cpasync16(smem_u32(Kb + row * LDK + c * 8),
                      kb + (size_t)(j0 + row) * Dn + c * 8);
            cpasync16(smem_u32(Vb + row * LDK + c * 8),
                      vb + (size_t)(j0 + row) * Dn + c * 8);
        }
        asm volatile("cp.async.commit_group;");
    };

    #pragma unroll
    for (int i = 0; i < 8; i++) {
        int idx = tid + i * 256;
        int row = idx >> 4;
        int c   = idx & 15;
        cpasync16(smem_u32(Qs + row * LDQ + c * 8),
                  qb + (size_t)(q0 + row) * Dn + c * 8);
    }
    asm volatile("cp.async.commit_group;");
    load_kv(0);
    asm volatile("cp.async.wait_group 0;" ::: "memory");
    __syncthreads();

    uint32_t qa[8][4];
    #pragma unroll
    for (int ks = 0; ks < 8; ks++)
        LDMX4(qa[ks], smem_u32(Qs + (w16 + a_r) * LDQ + ks * 16 + a_c));

    float acc[16][4] = {};
    float m0r = -1e30f, m1r = -1e30f, l0r = 0.0f, l1r = 0.0f;
    const float scale = 0.08838834764831845f;
    const int r0 = lane >> 2;
    const int pc = (lane & 3) * 2;
    const int qg0 = q0 + w16 + r0;
    const int qg1 = qg0 + 8;
    const int nkt = (q0 >> 6) + 2;

    for (int jt = 0; jt < nkt; jt++) {
        const int j0 = jt * 64;

        if (jt > 0) {
            asm volatile("cp.async.wait_group 0;" ::: "memory");
            __syncthreads();
        }
        if (jt + 1 < nkt) load_kv(jt + 1);

        const __half* Ks = smh + OFF_KV + (jt & 1) * 2 * KVBUF_H;
        const __half* Vs = Ks + KVBUF_H;

        float sc[8][4] = {};
        #pragma unroll
        for (int ks = 0; ks < 8; ks++) {
            uint32_t kb4[4][4];
            #pragma unroll
            for (int tp = 0; tp < 4; tp++)
                LDMX4(kb4[tp], smem_u32(Ks + (tp * 16 + b_r) * LDK + ks * 16 + b_c));
            #pragma unroll
            for (int t = 0; t < 8; t++)
                mma_f16(sc[t], qa[ks], &kb4[t >> 1][(t & 1) * 2]);
        }

        if (j0 + 63 > q0 + w16) {
            #pragma unroll
            for (int t = 0; t < 8; t++) {
                int c0 = j0 + t * 8 + pc;
                sc[t][0] = (c0     <= qg0) ? sc[t][0] * scale : -1e30f;
                sc[t][1] = (c0 + 1 <= qg0) ? sc[t][1] * scale : -1e30f;
                sc[t][2] = (c0     <= qg1) ? sc[t][2] * scale : -1e30f;
                sc[t][3] = (c0 + 1 <= qg1) ? sc[t][3] * scale : -1e30f;
            }
        } else {
            #pragma unroll
            for (int t = 0; t < 8; t++) {
                sc[t][0] *= scale; sc[t][1] *= scale;
                sc[t][2] *= scale; sc[t][3] *= scale;
            }
        }

        float mx0 = -1e30f, mx1 = -1e30f;
        #pragma unroll
        for (int t = 0; t < 8; t++) {
            mx0 = fmaxf(mx0, fmaxf(sc[t][0], sc[t][1]));
            mx1 = fmaxf(mx1, fmaxf(sc[t][2], sc[t][3]));
        }
        mx0 = fmaxf(mx0, __shfl_xor_sync(0xffffffffu, mx0, 1));
        mx0 = fmaxf(mx0, __shfl_xor_sync(0xffffffffu, mx0, 2));
        mx1 = fmaxf(mx1, __shfl_xor_sync(0xffffffffu, mx1, 1));
        mx1 = fmaxf(mx1, __shfl_xor_sync(0xffffffffu, mx1, 2));

        float nm0 = fmaxf(m0r, mx0), nm1 = fmaxf(m1r, mx1);
        float al0 = __expf(m0r - nm0), al1 = __expf(m1r - nm1);
        m0r = nm0; m1r = nm1;

        float s0 = 0.0f, s1 = 0.0f;
        #pragma unroll
        for (int t = 0; t < 8; t++) {
            sc[t][0] = __expf(sc[t][0] - nm0);
            sc[t][1] = __expf(sc[t][1] - nm0);
            sc[t][2] = __expf(sc[t][2] - nm1);
            sc[t][3] = __expf(sc[t][3] - nm1);
            s0 += sc[t][0] + sc[t][1];
            s1 += sc[t][2] + sc[t][3];
        }
        s0 += __shfl_xor_sync(0xffffffffu, s0, 1);
        s0 += __shfl_xor_sync(0xffffffffu, s0, 2);
        s1 += __shfl_xor_sync(0xffffffffu, s1, 1);
        s1 += __shfl_xor_sync(0xffffffffu, s1, 2);
        l0r = l0r * al0 + s0;
        l1r = l1r * al1 + s1;

        #pragma unroll
        for (int t = 0; t < 16; t++) {
            acc[t][0] *= al0; acc[t][1] *= al0;
            acc[t][2] *= al1; acc[t][3] *= al1;
        }

        #pragma unroll
        for (int t = 0; t < 8; t++) {
            *reinterpret_cast<__half2*>(Psh + (w16 + r0)     * LDP + t * 8 + pc) =
                __floats2half2_rn(sc[t][0], sc[t][1]);
            *reinterpret_cast<__half2*>(Psh + (w16 + r0 + 8) * LDP + t * 8 + pc) =
                __floats2half2_rn(sc[t][2], sc[t][3]);
        }
        __syncwarp();

        #pragma unroll
        for (int kp = 0; kp < 4; kp++) {
            uint32_t pa[4];
            LDMX4(pa, smem_u32(Psh + (w16 + a_r) * LDP + kp * 16 + a_c));
            #pragma unroll
            for (int dp = 0; dp < 8; dp++) {
                uint32_t vb4[4];
                LDMX4T(vb4, smem_u32(Vs + (kp * 16 + v_r) * LDK + dp * 16 + v_c));
                mma_f16(acc[dp * 2],     pa, &vb4[0]);
                mma_f16(acc[dp * 2 + 1], pa, &vb4[2]);
            }
        }
    }

    const int b = bh >> 4;
    const int h = bh & 15;
    const float inv0 = 1.0f / l0r;
    const float inv1 = 1.0f / l1r;
    size_t base0 = ((size_t)b * Sn + qg0) * (Hn * Dn) + h * Dn + pc;
    size_t base1 = ((size_t)b * Sn + qg1) * (Hn * Dn) + h * Dn + pc;
    #pragma unroll
    for (int t = 0; t < 16; t++) {
        *reinterpret_cast<__half2*>(ctx + base0 + t * 8) =
            __floats2half2_rn(acc[t][0] * inv0, acc[t][1] * inv0);
        *reinterpret_cast<__half2*>(ctx + base1 + t * 8) =
            __floats2half2_rn(acc[t][2] * inv1, acc[t][3] * inv1);
    }
}

// ---------------------------------------------------------------------------
// Launch
// ---------------------------------------------------------------------------
extern "C" void kernel_launch(void* const* d_in, const int* in_sizes, int n_in,
                              void* d_out, int out_size)
{
    const float* x  = (const float*)d_in[0];
    const float* Wq = (const float*)d_in[1];
    const float* Wk = (const float*)d_in[2];
    const float* Wv = (const float*)d_in[3];
    const float* Wo = (const float*)d_in[4];

    float* out = (float*)d_out;                    // [B,S,HID]
    float* kv  = out + (size_t)Bn * Sn * HIDn;     // [B,H,2,S,D]

    __half *xh, *wh, *qh, *kh, *vh, *ctxh;
    cudaGetSymbolAddress((void**)&xh,   g_xh);
    cudaGetSymbolAddress((void**)&wh,   g_wh);
    cudaGetSymbolAddress((void**)&qh,   g_qh);
    cudaGetSymbolAddress((void**)&kh,   g_kh);
    cudaGetSymbolAddress((void**)&vh,   g_vh);
    cudaGetSymbolAddress((void**)&ctxh, g_ctx);

    // 0) convert inputs to fp16 (2 launches)
    {
        int n4x = Mn * HIDn / 4;
        int n4w = HIDn * HIDn / 4;
        f2h<<<(n4x + 255) / 256, 256>>>((const float4*)x, (uint2*)xh, n4x);
        dim3 gw((n4w + 255) / 256, 4);
        f2h_w4<<<gw, 256>>>((const float4*)Wq, (const float4*)Wk,
                            (const float4*)Wv, (const float4*)Wo,
                            (uint2*)wh, n4w);
    }

    // 1) Q/K/V projections (K,V fp32 straight into kv cache + fp16 mirrors)
    cudaFuncSetAttribute(gemm_mma<0>, cudaFuncAttributeMaxDynamicSharedMemorySize, GEMM_SMEM);
    cudaFuncSetAttribute(gemm_mma<1>, cudaFuncAttributeMaxDynamicSharedMemorySize, GEMM_SMEM);
    dim3 gproj(HIDn / 128, Mn / 128, 3);
    gemm_mma<0><<<gproj, 256, GEMM_SMEM>>>(xh,
                                           wh + 0 * (size_t)HIDn * HIDn,
                                           wh + 1 * (size_t)HIDn * HIDn,
                                           wh + 2 * (size_t)HIDn * HIDn,
                                           kv, qh, kh, vh);

    // 2) causal flash attention (fp16 tensor cores, LPT order)
    cudaFuncSetAttribute(attn_mma, cudaFuncAttributeMaxDynamicSharedMemorySize, ATT_SMEM_B);
    dim3 gattn(Sn / 128, Bn * Hn);
    attn_mma<<<gattn, 256, ATT_SMEM_B>>>(qh, kh, vh, ctxh);

    // 3) output projection (fp32 result)
    dim3 gout(HIDn / 128, Mn / 128, 1);
    gemm_mma<1><<<gout, 256, GEMM_SMEM>>>(ctxh,
                                          wh + 3 * (size_t)HIDn * HIDn,
                                          nullptr, nullptr,
                                          out, nullptr, nullptr, nullptr);
}

// round 14
// speedup vs baseline: 1.5344x; 1.0285x over previous
#include <cuda_runtime.h>
#include <cuda_fp16.h>
#include <cstdint>

// Problem constants
#define Bn   4
#define Sn   2048
#define HIDn 2048
#define Hn   16
#define Dn   128
#define Mn   8192  // B*S

// Scratch (allocation-free rule: __device__ globals)
__device__ __half g_xh [(size_t)Mn * HIDn];            // x in fp16
__device__ __half g_wh [4][(size_t)HIDn * HIDn];       // Wq,Wk,Wv,Wo in fp16
__device__ __half g_qh [(size_t)Bn * Hn * Sn * Dn];    // Q fp16 [B,H,S,D]
__device__ __half g_kh [(size_t)Bn * Hn * Sn * Dn];    // K fp16 mirror
__device__ __half g_vh [(size_t)Bn * Hn * Sn * Dn];    // V fp16 mirror
__device__ __half g_ctx[(size_t)Mn * HIDn];            // ctx fp16 [B,S,H*D]

// ---------------------------------------------------------------------------
// helpers
// ---------------------------------------------------------------------------
__device__ __forceinline__ uint32_t smem_u32(const void* p) {
    uint32_t a;
    asm("{ .reg .u64 t; cvta.to.shared.u64 t, %1; cvt.u32.u64 %0, t; }"
        : "=r"(a) : "l"(p));
    return a;
}
__device__ __forceinline__ void cpasync16(uint32_t saddr, const void* g) {
    asm volatile("cp.async.cg.shared.global [%0], [%1], 16;" :: "r"(saddr), "l"(g));
}
__device__ __forceinline__ void mma_f16(float c[4], const uint32_t a[4], const uint32_t b[2]) {
    asm volatile("mma.sync.aligned.m16n8k16.row.col.f32.f16.f16.f32 "
                 "{%0,%1,%2,%3}, {%4,%5,%6,%7}, {%8,%9}, {%0,%1,%2,%3};"
                 : "+f"(c[0]), "+f"(c[1]), "+f"(c[2]), "+f"(c[3])
                 : "r"(a[0]), "r"(a[1]), "r"(a[2]), "r"(a[3]), "r"(b[0]), "r"(b[1]));
}
__device__ __forceinline__ uint32_t packh2(float lo, float hi) {
    __half2 h = __floats2half2_rn(lo, hi);
    return *reinterpret_cast<uint32_t*>(&h);
}
#define LDMX4(r, addr)                                                                  \
    asm volatile("ldmatrix.sync.aligned.m8n8.x4.shared.b16 {%0,%1,%2,%3}, [%4];"        \
                 : "=r"((r)[0]), "=r"((r)[1]), "=r"((r)[2]), "=r"((r)[3]) : "r"(addr))
#define LDMX4T(r, addr)                                                                 \
    asm volatile("ldmatrix.sync.aligned.m8n8.x4.trans.shared.b16 {%0,%1,%2,%3}, [%4];"  \
                 : "=r"((r)[0]), "=r"((r)[1]), "=r"((r)[2]), "=r"((r)[3]) : "r"(addr))

// ---------------------------------------------------------------------------
// fp32 -> fp16 conversion prepass
// ---------------------------------------------------------------------------
__global__ void __launch_bounds__(256) f2h(const float4* __restrict__ in,
                                           uint2* __restrict__ out, int n4) {
    int i = blockIdx.x * blockDim.x + threadIdx.x;
    if (i < n4) {
        float4 v = in[i];
        __half2 a = __floats2half2_rn(v.x, v.y);
        __half2 b = __floats2half2_rn(v.z, v.w);
        uint2 r;
        r.x = *reinterpret_cast<uint32_t*>(&a);
        r.y = *reinterpret_cast<uint32_t*>(&b);
        out[i] = r;
    }
}
__global__ void __launch_bounds__(256) f2h_w4(const float4* __restrict__ w0,
                                              const float4* __restrict__ w1,
                                              const float4* __restrict__ w2,
                                              const float4* __restrict__ w3,
                                              uint2* __restrict__ out, int n4) {
    const float4* srcs[4] = {w0, w1, w2, w3};
    const float4* in = srcs[blockIdx.y];
    uint2* dst = out + (size_t)blockIdx.y * n4;
    int i = blockIdx.x * blockDim.x + threadIdx.x;
    if (i < n4) {
        float4 v = in[i];
        __half2 a = __floats2half2_rn(v.x, v.y);
        __half2 b = __floats2half2_rn(v.z, v.w);
        uint2 r;
        r.x = *reinterpret_cast<uint32_t*>(&a);
        r.y = *reinterpret_cast<uint32_t*>(&b);
        dst[i] = r;
    }
}

// ---------------------------------------------------------------------------
// fp16 mma.sync NT-GEMM (R8 warp config; 4-stage cp.async pipeline)
// 256 thr = 8 warps (2m x 4n), warp tile 64x32, BK=32, 2 CTAs/SM.
// ---------------------------------------------------------------------------
#define LDW 40
#define TILE_H (128 * LDW)
#define STAGE_H (2 * TILE_H)
#define NSTG 4
#define GEMM_SMEM (NSTG * STAGE_H * 2)     // 81920 B

template<int MODE>
__global__ void __launch_bounds__(256, 2) gemm_mma(const __half* __restrict__ A_,
                                                   const __half* __restrict__ W0,
                                                   const __half* __restrict__ W1,
                                                   const __half* __restrict__ W2,
                                                   float* __restrict__ fout,
                                                   __half* __restrict__ hq,
                                                   __half* __restrict__ hk,
                                                   __half* __restrict__ hv)
{
    extern __shared__ __half smh[];

    const int tid  = threadIdx.x;
    const int wid  = tid >> 5;
    const int lane = tid & 31;
    const int wm = (wid >> 2) * 64;
    const int wn = (wid & 3) * 32;

    const int m0 = blockIdx.y * 128;
    const int n0 = blockIdx.x * 128;
    int z = 0;
    const __half* W = W0;
    if (MODE == 0) { z = blockIdx.z; W = (z == 0) ? W0 : (z == 1) ? W1 : W2; }

    const int mat = lane >> 3;
    const int a_r = (mat & 1) * 8 + (lane & 7);
    const int a_c = (mat >> 1) * 8;
    const int bx_r = (lane >> 4) * 8 + (lane & 7);
    const int bx_c = ((lane >> 3) & 1) * 8;

    float acc[4][4][4] = {};

    auto load_stage = [&](int j) {
        __half* As = smh + (j % NSTG) * STAGE_H;
        __half* Bs = As + TILE_H;
        const int k0 = j * 32;
        #pragma unroll
        for (int i = 0; i < 2; i++) {
            int idx = tid + i * 256;
            int row = idx >> 2;
            int c   = idx & 3;
            cpasync16(smem_u32(As + row * LDW + c * 8),
                      A_ + (size_t)(m0 + row) * HIDn + k0 + c * 8);
            cpasync16(smem_u32(Bs + row * LDW + c * 8),
                      W  + (size_t)(n0 + row) * HIDn + k0 + c * 8);
        }
        asm volatile("cp.async.commit_group;");
    };

    const int nk = HIDn / 32;
    load_stage(0);
    load_stage(1);
    load_stage(2);

    for (int j = 0; j < nk; j++) {
        if (j < nk - 3) {
            asm volatile("cp.async.wait_group 2;" ::: "memory");
        } else {
            asm volatile("cp.async.wait_group 0;" ::: "memory");
        }
        __syncthreads();
        if (j + 3 < nk) load_stage(j + 3);

        const __half* As = smh + (j % NSTG) * STAGE_H;
        const __half* Bs = As + TILE_H;

        #pragma unroll
        for (int ks = 0; ks < 2; ks++) {
            const int k0 = ks * 16;
            uint32_t a[4][4];
            #pragma unroll
            for (int i = 0; i < 4; i++)
                LDMX4(a[i], smem_u32(As + (wm + i * 16 + a_r) * LDW + k0 + a_c));
            uint32_t b4[2][4];
            #pragma unroll
            for (int tp = 0; tp < 2; tp++)
                LDMX4(b4[tp], smem_u32(Bs + (wn + tp * 16 + bx_r) * LDW + k0 + bx_c));
            #pragma unroll
            for (int i = 0; i < 4; i++)
                #pragma unroll
                for (int t = 0; t < 4; t++)
                    mma_f16(acc[i][t], a[i], &b4[t >> 1][(t & 1) * 2]);
        }
    }

    const int er = lane >> 2;
    const int ec = (lane & 3) * 2;

    #pragma unroll
    for (int i = 0; i < 4; i++) {
        const int r0 = m0 + wm + i * 16 + er;
        #pragma unroll
        for (int half = 0; half < 2; half++) {
            const int m = r0 + half * 8;
            if (MODE == 1) {
                size_t o = (size_t)m * HIDn + n0 + wn + ec;
                #pragma unroll
                for (int t = 0; t < 4; t++) {
                    float2 v = make_float2(acc[i][t][half * 2], acc[i][t][half * 2 + 1]);
                    *reinterpret_cast<float2*>(fout + o + t * 8) = v;
                }
            } else {
                const int b = m >> 11;
                const int s = m & (Sn - 1);
                const int h = n0 >> 7;
                const int d0 = wn + ec;
                size_t hb = (((size_t)(b * Hn + h)) * Sn + s) * Dn + d0;
                if (z == 0) {
                    #pragma unroll
                    for (int t = 0; t < 4; t++) {
                        __half2 hv2 = __floats2half2_rn(acc[i][t][half * 2], acc[i][t][half * 2 + 1]);
                        *reinterpret_cast<__half2*>(hq + hb + t * 8) = hv2;
                    }
                } else {
                    size_t fb = ((((size_t)(b * Hn + h)) * 2 + (z - 1)) * Sn + s) * Dn + d0;
                    __half* hm = (z == 1) ? hk : hv;
                    #pragma unroll
                    for (int t = 0; t < 4; t++) {
                        float2 v = make_float2(acc[i][t][half * 2], acc[i][t][half * 2 + 1]);
                        *reinterpret_cast<float2*>(fout + fb + t * 8) = v;
                        __half2 hv2 = __floats2half2_rn(v.x, v.y);
                        *reinterpret_cast<__half2*>(hm + hb + t * 8) = hv2;
                    }
                }
            }
        }
    }
}

// ---------------------------------------------------------------------------
// fp16 tensor-core causal flash attention (R8 config) with REGISTER-RESIDENT P:
// the m16n8 C-fragment of QK^T maps exactly onto the m16n8k16 A-fragment of
// PV (n(QK) == k(PV)) -> no P smem staging, no syncwarp, no P ldmatrix.
// ---------------------------------------------------------------------------
#define LDQ 136
#define LDK 136
#define KVBUF_H (64 * LDK)
#define OFF_KV  0
#define OFF_QS  (4 * KVBUF_H)                    // 34816
#define ATT_SMEM_H (OFF_QS + 128 * LDQ)          // 52224 halves
#define ATT_SMEM_B (ATT_SMEM_H * 2)              // 104448 bytes

__global__ void __launch_bounds__(256, 1) attn_mma(const __half* __restrict__ q,
                                                   const __half* __restrict__ kh,
                                                   const __half* __restrict__ vh,
                                                   __half* __restrict__ ctx)
{
    extern __shared__ __half smh[];
    __half* Qs = smh + OFF_QS;    // [128][LDQ]

    const int q0 = blockIdx.x * 128;
    const int bh = blockIdx.y;
    const __half* qb = q  + (size_t)bh * Sn * Dn;
    const __half* kb = kh + (size_t)bh * Sn * Dn;
    const __half* vb = vh + (size_t)bh * Sn * Dn;

    const int tid  = threadIdx.x;
    const int wid  = tid >> 5;
    const int lane = tid & 31;
    const int w16  = wid * 16;

    const int mat = lane >> 3;
    const int a_r = (mat & 1) * 8 + (lane & 7);
    const int a_c = (mat >> 1) * 8;
    const int b_r = (lane >> 4) * 8 + (lane & 7);
    const int b_c = ((lane >> 3) & 1) * 8;
    const int v_r = ((lane >> 3) & 1) * 8 + (lane & 7);
    const int v_c = (lane >> 4) * 8;

    auto load_kv = [&](int jt) {
        __half* Kb = smh + OFF_KV + (jt & 1) * 2 * KVBUF_H;
        __half* Vb = Kb + KVBUF_H;
        const int j0 = jt * 64;
        #pragma unroll
        for (int i = 0; i < 4; i++) {
            int idx = tid + i * 256;
            int row = idx >> 4;
            int c   = idx & 15;
            cpasync16(smem_u32(Kb + row * LDK + c * 8),
                      kb + (size_t)(j0 + row) * Dn + c * 8);
            cpasync16(smem_u32(Vb + row * LDK + c * 8),
                      vb + (size_t)(j0 + row) * Dn + c * 8);
        }
        asm volatile("cp.async.commit_group;");
    };

    #pragma unroll
    for (int i = 0; i < 8; i++) {
        int idx = tid + i * 256;
        int row = idx >> 4;
        int c   = idx & 15;
        cpasync16(smem_u32(Qs + row * LDQ + c * 8),
                  qb + (size_t)(q0 + row) * Dn + c * 8);
    }
    asm volatile("cp.async.commit_group;");
    load_kv(0);
    asm volatile("cp.async.wait_group 0;" ::: "memory");
    __syncthreads();

    uint32_t qa[8][4];
    #pragma unroll
    for (int ks = 0; ks < 8; ks++)
        LDMX4(qa[ks], smem_u32(Qs + (w16 + a_r) * LDQ + ks * 16 + a_c));

    float acc[16][4] = {};
    float m0r = -1e30f, m1r = -1e30f, l0r = 0.0f, l1r = 0.0f;
    const float scale = 0.08838834764831845f;
    const int r0 = lane >> 2;
    const int pc = (lane & 3) * 2;
    const int qg0 = q0 + w16 + r0;
    const int qg1 = qg0 + 8;
    const int nkt = (q0 >> 6) + 2;

    for (int jt = 0; jt < nkt; jt++) {
        const int j0 = jt * 64;

        if (jt > 0) {
            asm volatile("cp.async.wait_group 0;" ::: "memory");
            __syncthreads();
        }
        if (jt + 1 < nkt) load_kv(jt + 1);

        const __half* Ks = smh + OFF_KV + (jt & 1) * 2 * KVBUF_H;
        const __half* Vs = Ks + KVBUF_H;

        // ---- scores = Q K^T ----
        float sc[8][4] = {};
        #pragma unroll
        for (int ks = 0; ks < 8; ks++) {
            uint32_t kb4[4][4];
            #pragma unroll
            for (int tp = 0; tp < 4; tp++)
                LDMX4(kb4[tp], smem_u32(Ks + (tp * 16 + b_r) * LDK + ks * 16 + b_c));
            #pragma unroll
            for (int t = 0; t < 8; t++)
                mma_f16(sc[t], qa[ks], &kb4[t >> 1][(t & 1) * 2]);
        }

        // ---- scale + causal mask ----
        if (j0 + 63 > q0 + w16) {
            #pragma unroll
            for (int t = 0; t < 8; t++) {
                int c0 = j0 + t * 8 + pc;
                sc[t][0] = (c0     <= qg0) ? sc[t][0] * scale : -1e30f;
                sc[t][1] = (c0 + 1 <= qg0) ? sc[t][1] * scale : -1e30f;
                sc[t][2] = (c0     <= qg1) ? sc[t][2] * scale : -1e30f;
                sc[t][3] = (c0 + 1 <= qg1) ? sc[t][3] * scale : -1e30f;
            }
        } else {
            #pragma unroll
            for (int t = 0; t < 8; t++) {
                sc[t][0] *= scale; sc[t][1] *= scale;
                sc[t][2] *= scale; sc[t][3] *= scale;
            }
        }

        // ---- online softmax ----
        float mx0 = -1e30f, mx1 = -1e30f;
        #pragma unroll
        for (int t = 0; t < 8; t++) {
            mx0 = fmaxf(mx0, fmaxf(sc[t][0], sc[t][1]));
            mx1 = fmaxf(mx1, fmaxf(sc[t][2], sc[t][3]));
        }
        mx0 = fmaxf(mx0, __shfl_xor_sync(0xffffffffu, mx0, 1));
        mx0 = fmaxf(mx0, __shfl_xor_sync(0xffffffffu, mx0, 2));
        mx1 = fmaxf(mx1, __shfl_xor_sync(0xffffffffu, mx1, 1));
        mx1 = fmaxf(mx1, __shfl_xor_sync(0xffffffffu, mx1, 2));

        float nm0 = fmaxf(m0r, mx0), nm1 = fmaxf(m1r, mx1);
        float al0 = __expf(m0r - nm0), al1 = __expf(m1r - nm1);
        m0r = nm0; m1r = nm1;

        float s0 = 0.0f, s1 = 0.0f;
        #pragma unroll
        for (int t = 0; t < 8; t++) {
            sc[t][0] = __expf(sc[t][0] - nm0);
            sc[t][1] = __expf(sc[t][1] - nm0);
            sc[t][2] = __expf(sc[t][2] - nm1);
            sc[t][3] = __expf(sc[t][3] - nm1);
            s0 += sc[t][0] + sc[t][1];
            s1 += sc[t][2] + sc[t][3];
        }
        s0 += __shfl_xor_sync(0xffffffffu, s0, 1);
        s0 += __shfl_xor_sync(0xffffffffu, s0, 2);
        s1 += __shfl_xor_sync(0xffffffffu, s1, 1);
        s1 += __shfl_xor_sync(0xffffffffu, s1, 2);
        l0r = l0r * al0 + s0;
        l1r = l1r * al1 + s1;

        #pragma unroll
        for (int t = 0; t < 16; t++) {
            acc[t][0] *= al0; acc[t][1] *= al0;
            acc[t][2] *= al1; acc[t][3] *= al1;
        }

        // ---- acc += P V : P packed directly from QK C-fragments ----
        #pragma unroll
        for (int kp = 0; kp < 4; kp++) {
            uint32_t pa[4];
            pa[0] = packh2(sc[2 * kp][0],     sc[2 * kp][1]);
            pa[1] = packh2(sc[2 * kp][2],     sc[2 * kp][3]);
            pa[2] = packh2(sc[2 * kp + 1][0], sc[2 * kp + 1][1]);
            pa[3] = packh2(sc[2 * kp + 1][2], sc[2 * kp + 1][3]);
            #pragma unroll
            for (int dp = 0; dp < 8; dp++) {
                uint32_t vb4[4];
                LDMX4T(vb4, smem_u32(Vs + (kp * 16 + v_r) * LDK + dp * 16 + v_c));
                mma_f16(acc[dp * 2],     pa, &vb4[0]);
                mma_f16(acc[dp * 2 + 1], pa, &vb4[2]);
            }
        }
    }

    const int b = bh >> 4;
    const int h = bh & 15;
    const float inv0 = 1.0f / l0r;
    const float inv1 = 1.0f / l1r;
    size_t base0 = ((size_t)b * Sn + qg0) * (Hn * Dn) + h * Dn + pc;
    size_t base1 = ((size_t)b * Sn + qg1) * (Hn * Dn) + h * Dn + pc;
    #pragma unroll
    for (int t = 0; t < 16; t++) {
        *reinterpret_cast<__half2*>(ctx + base0 + t * 8) =
            __floats2half2_rn(acc[t][0] * inv0, acc[t][1] * inv0);
        *reinterpret_cast<__half2*>(ctx + base1 + t * 8) =
            __floats2half2_rn(acc[t][2] * inv1, acc[t][3] * inv1);
    }
}

// ---------------------------------------------------------------------------
// Launch
// ---------------------------------------------------------------------------
extern "C" void kernel_launch(void* const* d_in, const int* in_sizes, int n_in,
                              void* d_out, int out_size)
{
    const float* x  = (const float*)d_in[0];
    const float* Wq = (const float*)d_in[1];
    const float* Wk = (const float*)d_in[2];
    const float* Wv = (const float*)d_in[3];
    const float* Wo = (const float*)d_in[4];

    float* out = (float*)d_out;                    // [B,S,HID]
    float* kv  = out + (size_t)Bn * Sn * HIDn;     // [B,H,2,S,D]

    __half *xh, *wh, *qh, *kh, *vh, *ctxh;
    cudaGetSymbolAddress((void**)&xh,   g_xh);
    cudaGetSymbolAddress((void**)&wh,   g_wh);
    cudaGetSymbolAddress((void**)&qh,   g_qh);
    cudaGetSymbolAddress((void**)&kh,   g_kh);
    cudaGetSymbolAddress((void**)&vh,   g_vh);
    cudaGetSymbolAddress((void**)&ctxh, g_ctx);

    // 0) convert inputs to fp16 (2 launches)
    {
        int n4x = Mn * HIDn / 4;
        int n4w = HIDn * HIDn / 4;
        f2h<<<(n4x + 255) / 256, 256>>>((const float4*)x, (uint2*)xh, n4x);
        dim3 gw((n4w + 255) / 256, 4);
        f2h_w4<<<gw, 256>>>((const float4*)Wq, (const float4*)Wk,
                            (const float4*)Wv, (const float4*)Wo,
                            (uint2*)wh, n4w);
    }

    // 1) Q/K/V projections (K,V fp32 straight into kv cache + fp16 mirrors)
    cudaFuncSetAttribute(gemm_mma<0>, cudaFuncAttributeMaxDynamicSharedMemorySize, GEMM_SMEM);
    cudaFuncSetAttribute(gemm_mma<1>, cudaFuncAttributeMaxDynamicSharedMemorySize, GEMM_SMEM);
    dim3 gproj(HIDn / 128, Mn / 128, 3);
    gemm_mma<0><<<gproj, 256, GEMM_SMEM>>>(xh,
                                           wh + 0 * (size_t)HIDn * HIDn,
                                           wh + 1 * (size_t)HIDn * HIDn,
                                           wh + 2 * (size_t)HIDn * HIDn,
                                           kv, qh, kh, vh);

    // 2) causal flash attention (fp16 tensor cores, register-resident P)
    cudaFuncSetAttribute(attn_mma, cudaFuncAttributeMaxDynamicSharedMemorySize, ATT_SMEM_B);
    dim3 gattn(Sn / 128, Bn * Hn);
    attn_mma<<<gattn, 256, ATT_SMEM_B>>>(qh, kh, vh, ctxh);

    // 3) output projection (fp32 result)
    dim3 gout(HIDn / 128, Mn / 128, 1);
    gemm_mma<1><<<gout, 256, GEMM_SMEM>>>(ctxh,
                                          wh + 3 * (size_t)HIDn * HIDn,
                                          nullptr, nullptr,
                                          out, nullptr, nullptr, nullptr);
}

// round 15
// speedup vs baseline: 1.6341x; 1.0650x over previous
#include <cuda_runtime.h>
#include <cuda_fp16.h>
#include <cstdint>

// Problem constants
#define Bn   4
#define Sn   2048
#define HIDn 2048
#define Hn   16
#define Dn   128
#define Mn   8192  // B*S

// Scratch (allocation-free rule: __device__ globals)
__device__ __half g_xh [(size_t)Mn * HIDn];            // x in fp16
__device__ __half g_wh [4][(size_t)HIDn * HIDn];       // Wq,Wk,Wv,Wo in fp16
__device__ __half g_qh [(size_t)Bn * Hn * Sn * Dn];    // Q fp16 [B,H,S,D]
__device__ __half g_kh [(size_t)Bn * Hn * Sn * Dn];    // K fp16 mirror
__device__ __half g_vh [(size_t)Bn * Hn * Sn * Dn];    // V fp16 mirror
__device__ __half g_ctx[(size_t)Mn * HIDn];            // ctx fp16 [B,S,H*D]

// ---------------------------------------------------------------------------
// helpers
// ---------------------------------------------------------------------------
__device__ __forceinline__ uint32_t smem_u32(const void* p) {
    uint32_t a;
    asm("{ .reg .u64 t; cvta.to.shared.u64 t, %1; cvt.u32.u64 %0, t; }"
        : "=r"(a) : "l"(p));
    return a;
}
__device__ __forceinline__ void cpasync16(uint32_t saddr, const void* g) {
    asm volatile("cp.async.cg.shared.global [%0], [%1], 16;" :: "r"(saddr), "l"(g));
}
__device__ __forceinline__ void mma_f16(float c[4], const uint32_t a[4], const uint32_t b[2]) {
    asm volatile("mma.sync.aligned.m16n8k16.row.col.f32.f16.f16.f32 "
                 "{%0,%1,%2,%3}, {%4,%5,%6,%7}, {%8,%9}, {%0,%1,%2,%3};"
                 : "+f"(c[0]), "+f"(c[1]), "+f"(c[2]), "+f"(c[3])
                 : "r"(a[0]), "r"(a[1]), "r"(a[2]), "r"(a[3]), "r"(b[0]), "r"(b[1]));
}
__device__ __forceinline__ uint32_t packh2(float lo, float hi) {
    __half2 h = __floats2half2_rn(lo, hi);
    return *reinterpret_cast<uint32_t*>(&h);
}
__device__ __forceinline__ float ex2(float x) {
    float y;
    asm("ex2.approx.ftz.f32 %0, %1;" : "=f"(y) : "f"(x));
    return y;
}
#define LDMX4(r, addr)                                                                  \
    asm volatile("ldmatrix.sync.aligned.m8n8.x4.shared.b16 {%0,%1,%2,%3}, [%4];"        \
                 : "=r"((r)[0]), "=r"((r)[1]), "=r"((r)[2]), "=r"((r)[3]) : "r"(addr))
#define LDMX4T(r, addr)                                                                 \
    asm volatile("ldmatrix.sync.aligned.m8n8.x4.trans.shared.b16 {%0,%1,%2,%3}, [%4];"  \
                 : "=r"((r)[0]), "=r"((r)[1]), "=r"((r)[2]), "=r"((r)[3]) : "r"(addr))

// ---------------------------------------------------------------------------
// fp32 -> fp16 conversion prepass
// ---------------------------------------------------------------------------
__global__ void __launch_bounds__(256) f2h(const float4* __restrict__ in,
                                           uint2* __restrict__ out, int n4) {
    int i = blockIdx.x * blockDim.x + threadIdx.x;
    if (i < n4) {
        float4 v = in[i];
        __half2 a = __floats2half2_rn(v.x, v.y);
        __half2 b = __floats2half2_rn(v.z, v.w);
        uint2 r;
        r.x = *reinterpret_cast<uint32_t*>(&a);
        r.y = *reinterpret_cast<uint32_t*>(&b);
        out[i] = r;
    }
}
__global__ void __launch_bounds__(256) f2h_w4(const float4* __restrict__ w0,
                                              const float4* __restrict__ w1,
                                              const float4* __restrict__ w2,
                                              const float4* __restrict__ w3,
                                              uint2* __restrict__ out, int n4) {
    const float4* srcs[4] = {w0, w1, w2, w3};
    const float4* in = srcs[blockIdx.y];
    uint2* dst = out + (size_t)blockIdx.y * n4;
    int i = blockIdx.x * blockDim.x + threadIdx.x;
    if (i < n4) {
        float4 v = in[i];
        __half2 a = __floats2half2_rn(v.x, v.y);
        __half2 b = __floats2half2_rn(v.z, v.w);
        uint2 r;
        r.x = *reinterpret_cast<uint32_t*>(&a);
        r.y = *reinterpret_cast<uint32_t*>(&b);
        dst[i] = r;
    }
}

// ---------------------------------------------------------------------------
// fp16 mma.sync NT-GEMM: BK=64 (half the barriers of R14), 3-stage cp.async.
// 256 thr = 8 warps (2m x 4n), warp tile 64x32, 2 CTAs/SM.
// ---------------------------------------------------------------------------
#define KW 64                                // K columns per stage
#define LDW 72                               // row stride in halves (144B, LDSM-clean)
#define TILE_H (128 * LDW)
#define STAGE_H (2 * TILE_H)
#define NSTG 3
#define GEMM_SMEM (NSTG * STAGE_H * 2)       // 110592 B

template<int MODE>
__global__ void __launch_bounds__(256, 2) gemm_mma(const __half* __restrict__ A_,
                                                   const __half* __restrict__ W0,
                                                   const __half* __restrict__ W1,
                                                   const __half* __restrict__ W2,
                                                   float* __restrict__ fout,
                                                   __half* __restrict__ hq,
                                                   __half* __restrict__ hk,
                                                   __half* __restrict__ hv)
{
    extern __shared__ __half smh[];

    const int tid  = threadIdx.x;
    const int wid  = tid >> 5;
    const int lane = tid & 31;
    const int wm = (wid >> 2) * 64;
    const int wn = (wid & 3) * 32;

    const int m0 = blockIdx.y * 128;
    const int n0 = blockIdx.x * 128;
    int z = 0;
    const __half* W = W0;
    if (MODE == 0) { z = blockIdx.z; W = (z == 0) ? W0 : (z == 1) ? W1 : W2; }

    const int mat = lane >> 3;
    const int a_r = (mat & 1) * 8 + (lane & 7);
    const int a_c = (mat >> 1) * 8;
    const int bx_r = (lane >> 4) * 8 + (lane & 7);
    const int bx_c = ((lane >> 3) & 1) * 8;

    float acc[4][4][4] = {};

    auto load_stage = [&](int j) {
        __half* As = smh + (j % NSTG) * STAGE_H;
        __half* Bs = As + TILE_H;
        const int k0 = j * KW;
        #pragma unroll
        for (int i = 0; i < 8; i++) {
            int idx = tid + i * 256;             // 0..2047
            int row = idx >> 3;                  // 0..255
            int c   = idx & 7;                   // 16B chunk (8 halves)
            if (row < 128) {
                cpasync16(smem_u32(As + row * LDW + c * 8),
                          A_ + (size_t)(m0 + row) * HIDn + k0 + c * 8);
            } else {
                int r = row - 128;
                cpasync16(smem_u32(Bs + r * LDW + c * 8),
                          W + (size_t)(n0 + r) * HIDn + k0 + c * 8);
            }
        }
        asm volatile("cp.async.commit_group;");
    };

    const int nk = HIDn / KW;                    // 32
    load_stage(0);
    load_stage(1);

    for (int j = 0; j < nk; j++) {
        if (j < nk - 2) {
            asm volatile("cp.async.wait_group 1;" ::: "memory");
        } else {
            asm volatile("cp.async.wait_group 0;" ::: "memory");
        }
        __syncthreads();
        if (j + 2 < nk) load_stage(j + 2);

        const __half* As = smh + (j % NSTG) * STAGE_H;
        const __half* Bs = As + TILE_H;

        #pragma unroll
        for (int ks = 0; ks < 4; ks++) {
            const int k0 = ks * 16;
            uint32_t a[4][4];
            #pragma unroll
            for (int i = 0; i < 4; i++)
                LDMX4(a[i], smem_u32(As + (wm + i * 16 + a_r) * LDW + k0 + a_c));
            uint32_t b4[2][4];
            #pragma unroll
            for (int tp = 0; tp < 2; tp++)
                LDMX4(b4[tp], smem_u32(Bs + (wn + tp * 16 + bx_r) * LDW + k0 + bx_c));
            #pragma unroll
            for (int i = 0; i < 4; i++)
                #pragma unroll
                for (int t = 0; t < 4; t++)
                    mma_f16(acc[i][t], a[i], &b4[t >> 1][(t & 1) * 2]);
        }
    }

    const int er = lane >> 2;
    const int ec = (lane & 3) * 2;

    #pragma unroll
    for (int i = 0; i < 4; i++) {
        const int r0 = m0 + wm + i * 16 + er;
        #pragma unroll
        for (int half = 0; half < 2; half++) {
            const int m = r0 + half * 8;
            if (MODE == 1) {
                size_t o = (size_t)m * HIDn + n0 + wn + ec;
                #pragma unroll
                for (int t = 0; t < 4; t++) {
                    float2 v = make_float2(acc[i][t][half * 2], acc[i][t][half * 2 + 1]);
                    *reinterpret_cast<float2*>(fout + o + t * 8) = v;
                }
            } else {
                const int b = m >> 11;
                const int s = m & (Sn - 1);
                const int h = n0 >> 7;
                const int d0 = wn + ec;
                size_t hb = (((size_t)(b * Hn + h)) * Sn + s) * Dn + d0;
                if (z == 0) {
                    #pragma unroll
                    for (int t = 0; t < 4; t++) {
                        __half2 hv2 = __floats2half2_rn(acc[i][t][half * 2], acc[i][t][half * 2 + 1]);
                        *reinterpret_cast<__half2*>(hq + hb + t * 8) = hv2;
                    }
                } else {
                    size_t fb = ((((size_t)(b * Hn + h)) * 2 + (z - 1)) * Sn + s) * Dn + d0;
                    __half* hm = (z == 1) ? hk : hv;
                    #pragma unroll
                    for (int t = 0; t < 4; t++) {
                        float2 v = make_float2(acc[i][t][half * 2], acc[i][t][half * 2 + 1]);
                        *reinterpret_cast<float2*>(fout + fb + t * 8) = v;
                        __half2 hv2 = __floats2half2_rn(v.x, v.y);
                        *reinterpret_cast<__half2*>(hm + hb + t * 8) = hv2;
                    }
                }
            }
        }
    }
}

// ---------------------------------------------------------------------------
// fp16 tensor-core causal flash attention: register-resident P (R14),
// exp2-domain softmax (scale*log2e folded), per-warp dead-tile skip.
// ---------------------------------------------------------------------------
#define LDQ 136
#define LDK 136
#define KVBUF_H (64 * LDK)
#define OFF_KV  0
#define OFF_QS  (4 * KVBUF_H)                    // 34816
#define ATT_SMEM_H (OFF_QS + 128 * LDQ)          // 52224 halves
#define ATT_SMEM_B (ATT_SMEM_H * 2)              // 104448 bytes

__global__ void __launch_bounds__(256, 1) attn_mma(const __half* __restrict__ q,
                                                   const __half* __restrict__ kh,
                                                   const __half* __restrict__ vh,
                                                   __half* __restrict__ ctx)
{
    extern __shared__ __half smh[];
    __half* Qs = smh + OFF_QS;    // [128][LDQ]

    const int q0 = blockIdx.x * 128;
    const int bh = blockIdx.y;
    const __half* qb = q  + (size_t)bh * Sn * Dn;
    const __half* kb = kh + (size_t)bh * Sn * Dn;
    const __half* vb = vh + (size_t)bh * Sn * Dn;

    const int tid  = threadIdx.x;
    const int wid  = tid >> 5;
    const int lane = tid & 31;
    const int w16  = wid * 16;

    const int mat = lane >> 3;
    const int a_r = (mat & 1) * 8 + (lane & 7);
    const int a_c = (mat >> 1) * 8;
    const int b_r = (lane >> 4) * 8 + (lane & 7);
    const int b_c = ((lane >> 3) & 1) * 8;
    const int v_r = ((lane >> 3) & 1) * 8 + (lane & 7);
    const int v_c = (lane >> 4) * 8;

    auto load_kv = [&](int jt) {
        __half* Kb = smh + OFF_KV + (jt & 1) * 2 * KVBUF_H;
        __half* Vb = Kb + KVBUF_H;
        const int j0 = jt * 64;
        #pragma unroll
        for (int i = 0; i < 4; i++) {
            int idx = tid + i * 256;
            int row = idx >> 4;
            int c   = idx & 15;
            cpasync16(smem_u32(Kb + row * LDK + c * 8),
                      kb + (size_t)(j0 + row) * Dn + c * 8);
            cpasync16(smem_u32(Vb + row * LDK + c * 8),
                      vb + (size_t)(j0 + row) * Dn + c * 8);
        }
        asm volatile("cp.async.commit_group;");
    };

    #pragma unroll
    for (int i = 0; i < 8; i++) {
        int idx = tid + i * 256;
        int row = idx >> 4;
        int c   = idx & 15;
        cpasync16(smem_u32(Qs + row * LDQ + c * 8),
                  qb + (size_t)(q0 + row) * Dn + c * 8);
    }
    asm volatile("cp.async.commit_group;");
    load_kv(0);
    asm volatile("cp.async.wait_group 0;" ::: "memory");
    __syncthreads();

    uint32_t qa[8][4];
    #pragma unroll
    for (int ks = 0; ks < 8; ks++)
        LDMX4(qa[ks], smem_u32(Qs + (w16 + a_r) * LDQ + ks * 16 + a_c));

    float acc[16][4] = {};
    float m0r = -1e30f, m1r = -1e30f, l0r = 0.0f, l1r = 0.0f;
    // scale * log2(e): softmax runs in exp2 domain (raw ex2, no hidden FFMA)
    const float scale2 = 0.12751741f;
    const int r0 = lane >> 2;
    const int pc = (lane & 3) * 2;
    const int qg0 = q0 + w16 + r0;
    const int qg1 = qg0 + 8;
    const int row_hi = q0 + w16 + 15;   // warp's last q row
    const int nkt = (q0 >> 6) + 2;

    for (int jt = 0; jt < nkt; jt++) {
        const int j0 = jt * 64;

        if (jt > 0) {
            asm volatile("cp.async.wait_group 0;" ::: "memory");
            __syncthreads();
        }
        if (jt + 1 < nkt) load_kv(jt + 1);

        if (j0 > row_hi) continue;   // fully causal-masked for this warp: skip compute

        const __half* Ks = smh + OFF_KV + (jt & 1) * 2 * KVBUF_H;
        const __half* Vs = Ks + KVBUF_H;

        // ---- scores = Q K^T ----
        float sc[8][4] = {};
        #pragma unroll
        for (int ks = 0; ks < 8; ks++) {
            uint32_t kb4[4][4];
            #pragma unroll
            for (int tp = 0; tp < 4; tp++)
                LDMX4(kb4[tp], smem_u32(Ks + (tp * 16 + b_r) * LDK + ks * 16 + b_c));
            #pragma unroll
            for (int t = 0; t < 8; t++)
                mma_f16(sc[t], qa[ks], &kb4[t >> 1][(t & 1) * 2]);
        }

        // ---- scale (log2 domain) + causal mask ----
        if (j0 + 63 > row_hi - 15) {   // diagonal region for this warp
            #pragma unroll
            for (int t = 0; t < 8; t++) {
                int c0 = j0 + t * 8 + pc;
                sc[t][0] = (c0     <= qg0) ? sc[t][0] * scale2 : -1e30f;
                sc[t][1] = (c0 + 1 <= qg0) ? sc[t][1] * scale2 : -1e30f;
                sc[t][2] = (c0     <= qg1) ? sc[t][2] * scale2 : -1e30f;
                sc[t][3] = (c0 + 1 <= qg1) ? sc[t][3] * scale2 : -1e30f;
            }
        } else {
            #pragma unroll
            for (int t = 0; t < 8; t++) {
                sc[t][0] *= scale2; sc[t][1] *= scale2;
                sc[t][2] *= scale2; sc[t][3] *= scale2;
            }
        }

        // ---- online softmax (exp2 domain) ----
        float mx0 = -1e30f, mx1 = -1e30f;
        #pragma unroll
        for (int t = 0; t < 8; t++) {
            mx0 = fmaxf(mx0, fmaxf(sc[t][0], sc[t][1]));
            mx1 = fmaxf(mx1, fmaxf(sc[t][2], sc[t][3]));
        }
        mx0 = fmaxf(mx0, __shfl_xor_sync(0xffffffffu, mx0, 1));
        mx0 = fmaxf(mx0, __shfl_xor_sync(0xffffffffu, mx0, 2));
        mx1 = fmaxf(mx1, __shfl_xor_sync(0xffffffffu, mx1, 1));
        mx1 = fmaxf(mx1, __shfl_xor_sync(0xffffffffu, mx1, 2));

        float nm0 = fmaxf(m0r, mx0), nm1 = fmaxf(m1r, mx1);
        float al0 = ex2(m0r - nm0), al1 = ex2(m1r - nm1);
        m0r = nm0; m1r = nm1;

        float s0 = 0.0f, s1 = 0.0f;
        #pragma unroll
        for (int t = 0; t < 8; t++) {
            sc[t][0] = ex2(sc[t][0] - nm0);
            sc[t][1] = ex2(sc[t][1] - nm0);
            sc[t][2] = ex2(sc[t][2] - nm1);
            sc[t][3] = ex2(sc[t][3] - nm1);
            s0 += sc[t][0] + sc[t][1];
            s1 += sc[t][2] + sc[t][3];
        }
        s0 += __shfl_xor_sync(0xffffffffu, s0, 1);
        s0 += __shfl_xor_sync(0xffffffffu, s0, 2);
        s1 += __shfl_xor_sync(0xffffffffu, s1, 1);
        s1 += __shfl_xor_sync(0xffffffffu, s1, 2);
        l0r = l0r * al0 + s0;
        l1r = l1r * al1 + s1;

        #pragma unroll
        for (int t = 0; t < 16; t++) {
            acc[t][0] *= al0; acc[t][1] *= al0;
            acc[t][2] *= al1; acc[t][3] *= al1;
        }

        // ---- acc += P V : P packed directly from QK C-fragments ----
        #pragma unroll
        for (int kp = 0; kp < 4; kp++) {
            uint32_t pa[4];
            pa[0] = packh2(sc[2 * kp][0],     sc[2 * kp][1]);
            pa[1] = packh2(sc[2 * kp][2],     sc[2 * kp][3]);
            pa[2] = packh2(sc[2 * kp + 1][0], sc[2 * kp + 1][1]);
            pa[3] = packh2(sc[2 * kp + 1][2], sc[2 * kp + 1][3]);
            #pragma unroll
            for (int dp = 0; dp < 8; dp++) {
                uint32_t vb4[4];
                LDMX4T(vb4, smem_u32(Vs + (kp * 16 + v_r) * LDK + dp * 16 + v_c));
                mma_f16(acc[dp * 2],     pa, &vb4[0]);
                mma_f16(acc[dp * 2 + 1], pa, &vb4[2]);
            }
        }
    }

    const int b = bh >> 4;
    const int h = bh & 15;
    const float inv0 = 1.0f / l0r;
    const float inv1 = 1.0f / l1r;
    size_t base0 = ((size_t)b * Sn + qg0) * (Hn * Dn) + h * Dn + pc;
    size_t base1 = ((size_t)b * Sn + qg1) * (Hn * Dn) + h * Dn + pc;
    #pragma unroll
    for (int t = 0; t < 16; t++) {
        *reinterpret_cast<__half2*>(ctx + base0 + t * 8) =
            __floats2half2_rn(acc[t][0] * inv0, acc[t][1] * inv0);
        *reinterpret_cast<__half2*>(ctx + base1 + t * 8) =
            __floats2half2_rn(acc[t][2] * inv1, acc[t][3] * inv1);
    }
}

// ---------------------------------------------------------------------------
// Launch
// ---------------------------------------------------------------------------
extern "C" void kernel_launch(void* const* d_in, const int* in_sizes, int n_in,
                              void* d_out, int out_size)
{
    const float* x  = (const float*)d_in[0];
    const float* Wq = (const float*)d_in[1];
    const float* Wk = (const float*)d_in[2];
    const float* Wv = (const float*)d_in[3];
    const float* Wo = (const float*)d_in[4];

    float* out = (float*)d_out;                    // [B,S,HID]
    float* kv  = out + (size_t)Bn * Sn * HIDn;     // [B,H,2,S,D]

    __half *xh, *wh, *qh, *kh, *vh, *ctxh;
    cudaGetSymbolAddress((void**)&xh,   g_xh);
    cudaGetSymbolAddress((void**)&wh,   g_wh);
    cudaGetSymbolAddress((void**)&qh,   g_qh);
    cudaGetSymbolAddress((void**)&kh,   g_kh);
    cudaGetSymbolAddress((void**)&vh,   g_vh);
    cudaGetSymbolAddress((void**)&ctxh, g_ctx);

    // 0) convert inputs to fp16 (2 launches)
    {
        int n4x = Mn * HIDn / 4;
        int n4w = HIDn * HIDn / 4;
        f2h<<<(n4x + 255) / 256, 256>>>((const float4*)x, (uint2*)xh, n4x);
        dim3 gw((n4w + 255) / 256, 4);
        f2h_w4<<<gw, 256>>>((const float4*)Wq, (const float4*)Wk,
                            (const float4*)Wv, (const float4*)Wo,
                            (uint2*)wh, n4w);
    }

    // 1) Q/K/V projections (K,V fp32 straight into kv cache + fp16 mirrors)
    cudaFuncSetAttribute(gemm_mma<0>, cudaFuncAttributeMaxDynamicSharedMemorySize, GEMM_SMEM);
    cudaFuncSetAttribute(gemm_mma<1>, cudaFuncAttributeMaxDynamicSharedMemorySize, GEMM_SMEM);
    dim3 gproj(HIDn / 128, Mn / 128, 3);
    gemm_mma<0><<<gproj, 256, GEMM_SMEM>>>(xh,
                                           wh + 0 * (size_t)HIDn * HIDn,
                                           wh + 1 * (size_t)HIDn * HIDn,
                                           wh + 2 * (size_t)HIDn * HIDn,
                                           kv, qh, kh, vh);

    // 2) causal flash attention
    cudaFuncSetAttribute(attn_mma, cudaFuncAttributeMaxDynamicSharedMemorySize, ATT_SMEM_B);
    dim3 gattn(Sn / 128, Bn * Hn);
    attn_mma<<<gattn, 256, ATT_SMEM_B>>>(qh, kh, vh, ctxh);

    // 3) output projection (fp32 result)
    dim3 gout(HIDn / 128, Mn / 128, 1);
    gemm_mma<1><<<gout, 256, GEMM_SMEM>>>(ctxh,
                                          wh + 3 * (size_t)HIDn * HIDn,
                                          nullptr, nullptr,
                                          out, nullptr, nullptr, nullptr);
}